// round 9
// baseline (speedup 1.0000x reference)
#include <cuda_runtime.h>
#include <math.h>
#include <stdint.h>

#define BB 2
#define SS 2048
#define HH 1024
#define FF 2816
#define EE 8
#define KK 2
#define TT (BB*SS)
#define SLOTS (TT*KK)
#define BM 128
#define PADMAX (SLOTS + EE*BM)    // 9216
#define RT_MAX (PADMAX/BM)        // 72
#define PITCH 136

__device__ float g_h1[(size_t)PADMAX * FF];
__device__ float g_y [(size_t)PADMAX * HH];
__device__ int   g_count[EE];
__device__ int   g_fill[EE];
__device__ float g_psum[EE];
__device__ int   g_base[EE+1];
__device__ int   g_sorted_token[PADMAX];
__device__ int   g_slot_row[SLOTS];
__device__ int   g_tok_e[SLOTS];
__device__ float g_tok_w[SLOTS];

__device__ __forceinline__ uint32_t to_tf32(float x) {
    uint32_t r; asm("cvt.rna.tf32.f32 %0, %1;" : "=r"(r) : "f"(x)); return r;
}
__device__ __forceinline__ void split_tf32(float x, uint32_t& hi, uint32_t& lo) {
    hi = to_tf32(x);
    lo = to_tf32(x - __uint_as_float(hi));
}
__device__ __forceinline__ void mma_tf32(float* d, const uint32_t* a, uint32_t b0, uint32_t b1) {
    asm volatile("mma.sync.aligned.m16n8k8.row.col.f32.tf32.tf32.f32 "
                 "{%0,%1,%2,%3}, {%4,%5,%6,%7}, {%8,%9}, {%0,%1,%2,%3};"
                 : "+f"(d[0]), "+f"(d[1]), "+f"(d[2]), "+f"(d[3])
                 : "r"(a[0]), "r"(a[1]), "r"(a[2]), "r"(a[3]), "r"(b0), "r"(b1));
}

__global__ void init_kernel() {
    int i = blockIdx.x * blockDim.x + threadIdx.x;
    if (i < PADMAX) g_sorted_token[i] = 0;
    if (i < EE) { g_count[i] = 0; g_fill[i] = 0; g_psum[i] = 0.f; }
}

__global__ void router_kernel(const float* __restrict__ x, const float* __restrict__ rw) {
    int t = blockIdx.x;
    __shared__ float sp[128][EE];
    float acc[EE];
#pragma unroll
    for (int e = 0; e < EE; e++) acc[e] = 0.f;
    const float* xt = x + (size_t)t * HH;
    for (int h = threadIdx.x; h < HH; h += 128) {
        float xv = xt[h];
#pragma unroll
        for (int e = 0; e < EE; e++) acc[e] += xv * rw[e*HH + h];
    }
#pragma unroll
    for (int e = 0; e < EE; e++) sp[threadIdx.x][e] = acc[e];
    __syncthreads();
    for (int s = 64; s > 0; s >>= 1) {
        if (threadIdx.x < s)
#pragma unroll
            for (int e = 0; e < EE; e++) sp[threadIdx.x][e] += sp[threadIdx.x + s][e];
        __syncthreads();
    }
    if (threadIdx.x == 0) {
        float lg[EE];
#pragma unroll
        for (int e = 0; e < EE; e++) lg[e] = sp[0][e];
        int i0 = 0;
#pragma unroll
        for (int e = 1; e < EE; e++) if (lg[e] > lg[i0]) i0 = e;
        int i1 = -1;
#pragma unroll
        for (int e = 0; e < EE; e++) {
            if (e == i0) continue;
            if (i1 < 0 || lg[e] > lg[i1]) i1 = e;
        }
        float ex = expf(lg[i1] - lg[i0]);
        g_tok_e[2*t] = i0;  g_tok_e[2*t+1] = i1;
        g_tok_w[2*t] = 1.f/(1.f+ex);  g_tok_w[2*t+1] = ex/(1.f+ex);
        atomicAdd(&g_count[i0], 1);
        atomicAdd(&g_count[i1], 1);
        float m = lg[0];
#pragma unroll
        for (int e = 1; e < EE; e++) m = fmaxf(m, lg[e]);
        float s = 0.f, pe[EE];
#pragma unroll
        for (int e = 0; e < EE; e++) { pe[e] = expf(lg[e] - m); s += pe[e]; }
        float inv = 1.f / s;
#pragma unroll
        for (int e = 0; e < EE; e++) atomicAdd(&g_psum[e], pe[e] * inv);
    }
}

__global__ void setup_kernel(float* __restrict__ out_aux) {
    if (threadIdx.x == 0) {
        int base = 0;
        for (int e = 0; e < EE; e++) {
            g_base[e] = base;
            base += (g_count[e] + BM - 1) & ~(BM - 1);
        }
        g_base[EE] = base;
        float aux = 0.f;
        for (int e = 0; e < EE; e++)
            aux += ((float)g_count[e] / SLOTS) * (g_psum[e] / TT);
        out_aux[0] = aux * EE;
    }
}

__global__ void scatter_kernel() {
    int s = blockIdx.x * blockDim.x + threadIdx.x;
    if (s >= SLOTS) return;
    int e = g_tok_e[s];
    int row = g_base[e] + atomicAdd(&g_fill[e], 1);
    g_sorted_token[row] = s >> 1;
    g_slot_row[s] = row;
}

// ==== GEMM1: h1 = silu(x@Wg)*(x@Wu). CTA 128M x 64F (gate/up interleaved cols) ====
__global__ __launch_bounds__(512) void gemm1_kernel(
    const float* __restrict__ x, const float* __restrict__ wg, const float* __restrict__ wu)
{
    int r0 = blockIdx.x * BM;
    if (r0 >= g_base[EE]) return;
    int n0f = blockIdx.y * 64;
    int e = 0;
    while (g_base[e+1] <= r0) e++;
    const float* Wg = wg + (size_t)e * HH * FF;
    const float* Wu = wu + (size_t)e * HH * FF;

    __shared__ float As[2][8][PITCH];
    __shared__ uint32_t Bhi[2][8][PITCH];
    __shared__ uint32_t Blo[2][8][PITCH];
    __shared__ int s_tok[128];

    int tid = threadIdx.x;
    if (tid < 128) s_tok[tid] = g_sorted_token[r0 + tid];
    __syncthreads();

    bool isA = tid < 256;
    int t = isA ? tid : tid - 256;
    int am = t & 127, kq4 = (t >> 7) * 4;        // A role
    int brw = t >> 5, fp = t & 31;               // B role: row 0-7, f-pair 0-31

    const float* arow = x + (size_t)s_tok[am] * HH + kq4;
    const int chunks = HH / 8;                   // 128

    // prologue: chunk 0 direct
    if (isA) {
        float4 v = *(const float4*)(arow);
        As[0][kq4+0][am]=v.x; As[0][kq4+1][am]=v.y; As[0][kq4+2][am]=v.z; As[0][kq4+3][am]=v.w;
    } else {
        float2 g = *(const float2*)(Wg + (size_t)brw * FF + n0f + 2*fp);
        float2 u = *(const float2*)(Wu + (size_t)brw * FF + n0f + 2*fp);
        uint32_t h0,l0,h1,l1,h2,l2,h3,l3;
        split_tf32(g.x,h0,l0); split_tf32(u.x,h1,l1); split_tf32(g.y,h2,l2); split_tf32(u.y,h3,l3);
        *(uint2*)&Bhi[0][brw][4*fp]   = make_uint2(h0,h1);
        *(uint2*)&Bhi[0][brw][4*fp+2] = make_uint2(h2,h3);
        *(uint2*)&Blo[0][brw][4*fp]   = make_uint2(l0,l1);
        *(uint2*)&Blo[0][brw][4*fp+2] = make_uint2(l2,l3);
    }
    // prefetch chunk 1
    float4 pA; float2 pG, pU;
    if (isA) pA = *(const float4*)(arow + 8);
    else {
        pG = *(const float2*)(Wg + (size_t)(8 + brw) * FF + n0f + 2*fp);
        pU = *(const float2*)(Wu + (size_t)(8 + brw) * FF + n0f + 2*fp);
    }
    __syncthreads();

    int lane = tid & 31, wid = tid >> 5;
    int wm = (wid & 3) * 32, wn = (wid >> 2) * 32;
    int fr = lane >> 2, kq = lane & 3;

    float d[2][4][4];
#pragma unroll
    for (int i = 0; i < 2; i++)
#pragma unroll
        for (int j = 0; j < 4; j++)
#pragma unroll
            for (int k = 0; k < 4; k++) d[i][j][k] = 0.f;

    for (int c = 0; c < chunks; c++) {
        int s = c & 1;
        if (c + 1 < chunks) {   // STS chunk c+1 -> stage s^1
            int s1 = s ^ 1;
            if (isA) {
                As[s1][kq4+0][am]=pA.x; As[s1][kq4+1][am]=pA.y; As[s1][kq4+2][am]=pA.z; As[s1][kq4+3][am]=pA.w;
            } else {
                uint32_t h0,l0,h1,l1,h2,l2,h3,l3;
                split_tf32(pG.x,h0,l0); split_tf32(pU.x,h1,l1); split_tf32(pG.y,h2,l2); split_tf32(pU.y,h3,l3);
                *(uint2*)&Bhi[s1][brw][4*fp]   = make_uint2(h0,h1);
                *(uint2*)&Bhi[s1][brw][4*fp+2] = make_uint2(h2,h3);
                *(uint2*)&Blo[s1][brw][4*fp]   = make_uint2(l0,l1);
                *(uint2*)&Blo[s1][brw][4*fp+2] = make_uint2(l2,l3);
            }
        }
        if (c + 2 < chunks) {   // LDG chunk c+2
            if (isA) pA = *(const float4*)(arow + (c+2)*8);
            else {
                pG = *(const float2*)(Wg + (size_t)((c+2)*8 + brw) * FF + n0f + 2*fp);
                pU = *(const float2*)(Wu + (size_t)((c+2)*8 + brw) * FF + n0f + 2*fp);
            }
        }
        // fragments
        uint32_t ahi[2][4], alo[2][4];
#pragma unroll
        for (int mt = 0; mt < 2; mt++) {
            int mb = wm + mt*16 + fr;
            split_tf32(As[s][kq][mb],     ahi[mt][0], alo[mt][0]);
            split_tf32(As[s][kq][mb+8],   ahi[mt][1], alo[mt][1]);
            split_tf32(As[s][kq+4][mb],   ahi[mt][2], alo[mt][2]);
            split_tf32(As[s][kq+4][mb+8], ahi[mt][3], alo[mt][3]);
        }
        uint32_t bh[4][2], bl[4][2];
#pragma unroll
        for (int nt = 0; nt < 4; nt++) {
            int nn = wn + nt*8 + fr;
            bh[nt][0] = Bhi[s][kq][nn];   bh[nt][1] = Bhi[s][kq+4][nn];
            bl[nt][0] = Blo[s][kq][nn];   bl[nt][1] = Blo[s][kq+4][nn];
        }
#pragma unroll
        for (int mt = 0; mt < 2; mt++)
#pragma unroll
            for (int nt = 0; nt < 4; nt++) {
                mma_tf32(d[mt][nt], ahi[mt], bh[nt][0], bh[nt][1]);
                mma_tf32(d[mt][nt], ahi[mt], bl[nt][0], bl[nt][1]);
                mma_tf32(d[mt][nt], alo[mt], bh[nt][0], bh[nt][1]);
            }
        __syncthreads();
    }

#pragma unroll
    for (int mt = 0; mt < 2; mt++) {
        int row = r0 + wm + mt*16 + fr;
#pragma unroll
        for (int nt = 0; nt < 4; nt++) {
            int f = n0f + (wn >> 1) + nt*4 + kq;
            float gv = d[mt][nt][0], uv = d[mt][nt][1];
            g_h1[(size_t)row * FF + f] = (gv / (1.f + expf(-gv))) * uv;
            gv = d[mt][nt][2]; uv = d[mt][nt][3];
            g_h1[(size_t)(row+8) * FF + f] = (gv / (1.f + expf(-gv))) * uv;
        }
    }
}

// ==== GEMM2: y = h1 @ Wd. CTA 128M x 128N ====
__global__ __launch_bounds__(512) void gemm2_kernel(const float* __restrict__ wd)
{
    int r0 = blockIdx.x * BM;
    if (r0 >= g_base[EE]) return;
    int n0 = blockIdx.y * 128;
    int e = 0;
    while (g_base[e+1] <= r0) e++;
    const float* Wd = wd + (size_t)e * FF * HH;

    __shared__ float As[2][8][PITCH];
    __shared__ uint32_t Bhi[2][8][PITCH];
    __shared__ uint32_t Blo[2][8][PITCH];

    int tid = threadIdx.x;
    bool isA = tid < 256;
    int t = isA ? tid : tid - 256;
    int am = t & 127, kq4 = (t >> 7) * 4;
    int brw = t >> 5, n4 = (t & 31) * 4;

    const float* arow = g_h1 + (size_t)(r0 + am) * FF + kq4;
    const int chunks = FF / 8;   // 352

    if (isA) {
        float4 v = *(const float4*)(arow);
        As[0][kq4+0][am]=v.x; As[0][kq4+1][am]=v.y; As[0][kq4+2][am]=v.z; As[0][kq4+3][am]=v.w;
    } else {
        float4 b = *(const float4*)(Wd + (size_t)brw * HH + n0 + n4);
        uint32_t h0,l0,h1,l1,h2,l2,h3,l3;
        split_tf32(b.x,h0,l0); split_tf32(b.y,h1,l1); split_tf32(b.z,h2,l2); split_tf32(b.w,h3,l3);
        *(uint2*)&Bhi[0][brw][n4]   = make_uint2(h0,h1);
        *(uint2*)&Bhi[0][brw][n4+2] = make_uint2(h2,h3);
        *(uint2*)&Blo[0][brw][n4]   = make_uint2(l0,l1);
        *(uint2*)&Blo[0][brw][n4+2] = make_uint2(l2,l3);
    }
    float4 pA, pB;
    if (isA) pA = *(const float4*)(arow + 8);
    else     pB = *(const float4*)(Wd + (size_t)(8 + brw) * HH + n0 + n4);
    __syncthreads();

    int lane = tid & 31, wid = tid >> 5;
    int wm = (wid & 3) * 32, wn = (wid >> 2) * 32;
    int fr = lane >> 2, kq = lane & 3;

    float d[2][4][4];
#pragma unroll
    for (int i = 0; i < 2; i++)
#pragma unroll
        for (int j = 0; j < 4; j++)
#pragma unroll
            for (int k = 0; k < 4; k++) d[i][j][k] = 0.f;

    for (int c = 0; c < chunks; c++) {
        int s = c & 1;
        if (c + 1 < chunks) {
            int s1 = s ^ 1;
            if (isA) {
                As[s1][kq4+0][am]=pA.x; As[s1][kq4+1][am]=pA.y; As[s1][kq4+2][am]=pA.z; As[s1][kq4+3][am]=pA.w;
            } else {
                uint32_t h0,l0,h1,l1,h2,l2,h3,l3;
                split_tf32(pB.x,h0,l0); split_tf32(pB.y,h1,l1); split_tf32(pB.z,h2,l2); split_tf32(pB.w,h3,l3);
                *(uint2*)&Bhi[s1][brw][n4]   = make_uint2(h0,h1);
                *(uint2*)&Bhi[s1][brw][n4+2] = make_uint2(h2,h3);
                *(uint2*)&Blo[s1][brw][n4]   = make_uint2(l0,l1);
                *(uint2*)&Blo[s1][brw][n4+2] = make_uint2(l2,l3);
            }
        }
        if (c + 2 < chunks) {
            if (isA) pA = *(const float4*)(arow + (c+2)*8);
            else     pB = *(const float4*)(Wd + (size_t)((c+2)*8 + brw) * HH + n0 + n4);
        }
        uint32_t ahi[2][4], alo[2][4];
#pragma unroll
        for (int mt = 0; mt < 2; mt++) {
            int mb = wm + mt*16 + fr;
            split_tf32(As[s][kq][mb],     ahi[mt][0], alo[mt][0]);
            split_tf32(As[s][kq][mb+8],   ahi[mt][1], alo[mt][1]);
            split_tf32(As[s][kq+4][mb],   ahi[mt][2], alo[mt][2]);
            split_tf32(As[s][kq+4][mb+8], ahi[mt][3], alo[mt][3]);
        }
        uint32_t bh[4][2], bl[4][2];
#pragma unroll
        for (int nt = 0; nt < 4; nt++) {
            int nn = wn + nt*8 + fr;
            bh[nt][0] = Bhi[s][kq][nn];   bh[nt][1] = Bhi[s][kq+4][nn];
            bl[nt][0] = Blo[s][kq][nn];   bl[nt][1] = Blo[s][kq+4][nn];
        }
#pragma unroll
        for (int mt = 0; mt < 2; mt++)
#pragma unroll
            for (int nt = 0; nt < 4; nt++) {
                mma_tf32(d[mt][nt], ahi[mt], bh[nt][0], bh[nt][1]);
                mma_tf32(d[mt][nt], ahi[mt], bl[nt][0], bl[nt][1]);
                mma_tf32(d[mt][nt], alo[mt], bh[nt][0], bh[nt][1]);
            }
        __syncthreads();
    }

#pragma unroll
    for (int mt = 0; mt < 2; mt++) {
        int row = r0 + wm + mt*16 + fr;
#pragma unroll
        for (int nt = 0; nt < 4; nt++) {
            int col = n0 + wn + nt*8 + 2*kq;
            *(float2*)&g_y[(size_t)row * HH + col]     = make_float2(d[mt][nt][0], d[mt][nt][1]);
            *(float2*)&g_y[(size_t)(row+8) * HH + col] = make_float2(d[mt][nt][2], d[mt][nt][3]);
        }
    }
}

__global__ void combine_kernel(float* __restrict__ out) {
    int i = blockIdx.x * blockDim.x + threadIdx.x;
    if (i >= TT * (HH/4)) return;
    int t = i / (HH/4);
    int c = (i - t * (HH/4)) * 4;
    int r0 = g_slot_row[2*t], r1 = g_slot_row[2*t+1];
    float w0 = g_tok_w[2*t], w1 = g_tok_w[2*t+1];
    float4 y0 = *(const float4*)(g_y + (size_t)r0 * HH + c);
    float4 y1 = *(const float4*)(g_y + (size_t)r1 * HH + c);
    float4 o;
    o.x = w0*y0.x + w1*y1.x;  o.y = w0*y0.y + w1*y1.y;
    o.z = w0*y0.z + w1*y1.z;  o.w = w0*y0.w + w1*y1.w;
    *(float4*)(out + (size_t)t * HH + c) = o;
}

extern "C" void kernel_launch(void* const* d_in, const int* in_sizes, int n_in,
                              void* d_out, int out_size) {
    const float* x  = (const float*)d_in[0];
    const float* rw = (const float*)d_in[1];
    const float* wg = (const float*)d_in[2];
    const float* wu = (const float*)d_in[3];
    const float* wd = (const float*)d_in[4];
    float* out = (float*)d_out;

    init_kernel<<<(PADMAX + 255) / 256, 256>>>();
    router_kernel<<<TT, 128>>>(x, rw);
    setup_kernel<<<1, 32>>>(out + (size_t)TT * HH);
    scatter_kernel<<<(SLOTS + 255) / 256, 256>>>();
    gemm1_kernel<<<dim3(RT_MAX, FF/64), 512>>>(x, wg, wu);
    gemm2_kernel<<<dim3(RT_MAX, HH/128), 512>>>(wd);
    combine_kernel<<<(TT * (HH/4) + 255) / 256, 256>>>(out);
}